// round 12
// baseline (speedup 1.0000x reference)
#include <cuda_runtime.h>
#include <cuda_fp16.h>
#include <cstdint>

// Problem: N=8,S=2048 -> T=16384 tokens, D=O=2048, E=8, top-2
#define T_TOKENS 16384
#define DIM_D    2048
#define DIM_O    2048
#define N_EXP    8
#define MAX_TILES 264               // ceil-per-expert padding worst case
#define R_MAX    (MAX_TILES * 128)  // padded rows

#define BM 128
#define BN 256
#define BK 64
#define NSTAGE 4
#define A_STAGE (BM * BK * 2)       // 16384 B
#define B_STAGE (BN * BK * 2)       // 32768 B
#define SMEM_TOTAL (NSTAGE * (A_STAGE + B_STAGE) + 512)   // 197120 B

#define GATE_BLKS (T_TOKENS / 32)   // 512: 8 warps/block x 4 tokens/warp
#define WT_BLKS   (32 * 32 * N_EXP) // 8192

// ---------------- device scratch (static; no allocation) ----------------
__device__ __half g_operm[(size_t)R_MAX * DIM_O];           // relu(XW+b) rows (fp16)
__device__ __half g_xh[(size_t)T_TOKENS * DIM_D];           // x fp16 (token order)
__device__ __half g_wt[(size_t)N_EXP * DIM_O * DIM_D];      // W^T fp16 [e][o][d]
__device__ int g_top[T_TOKENS * 2];
__device__ int g_counts[N_EXP];
__device__ int g_offsets[N_EXP];
__device__ int g_cursor[N_EXP];
__device__ int g_rows[R_MAX];        // padded row -> token (valid only < offset+count)
__device__ int g_pos[T_TOKENS * 2];  // (token,k) -> padded row
__device__ int g_tile_e[MAX_TILES];
__device__ int g_tile_r0[MAX_TILES];
__device__ int g_num_tiles;

// ---------------- helpers ----------------
__device__ __forceinline__ uint32_t smem_u32(const void* p) {
    uint32_t a;
    asm("{ .reg .u64 t; cvta.to.shared.u64 t, %1; cvt.u32.u64 %0, t; }" : "=r"(a) : "l"(p));
    return a;
}
__device__ __forceinline__ void cpa(uint32_t dst, const void* src, int n) {
    asm volatile("cp.async.ca.shared.global [%0], [%1], 16, %2;"
                 :: "r"(dst), "l"(src), "r"(n) : "memory");
}
#define CP_COMMIT() asm volatile("cp.async.commit_group;" ::: "memory")
#define CP_WAIT2()  asm volatile("cp.async.wait_group 2;" ::: "memory")
__device__ __forceinline__ void ldsm4(uint32_t* r, uint32_t addr) {
    asm volatile("ldmatrix.sync.aligned.m8n8.x4.shared.b16 {%0,%1,%2,%3}, [%4];"
                 : "=r"(r[0]), "=r"(r[1]), "=r"(r[2]), "=r"(r[3]) : "r"(addr));
}
__device__ __forceinline__ void mma_f16(float* d, const uint32_t* a, uint32_t b0, uint32_t b1) {
    asm volatile(
        "mma.sync.aligned.m16n8k16.row.col.f32.f16.f16.f32 "
        "{%0,%1,%2,%3}, {%4,%5,%6,%7}, {%8,%9}, {%0,%1,%2,%3};"
        : "+f"(d[0]), "+f"(d[1]), "+f"(d[2]), "+f"(d[3])
        : "r"(a[0]), "r"(a[1]), "r"(a[2]), "r"(a[3]), "r"(b0), "r"(b1));
}
// swizzled byte offset within a stage: row*128 + 16*(chunk ^ (row&7))
__device__ __forceinline__ int swz(int row, int chunk) {
    return row * 128 + ((chunk ^ (row & 7)) << 4);
}

// ---------------- init ----------------
__global__ void init_k() {
    int i = threadIdx.x;
    if (i < N_EXP) { g_counts[i] = 0; g_cursor[i] = 0; }
}

// ---------------- fused prep: gate(+x->fp16, 4 tok/warp)  ||  W transpose+convert ----------------
__global__ void prep_k(const float* __restrict__ x,
                       const float* __restrict__ gw,
                       const float* __restrict__ gb,
                       const float* __restrict__ ew) {
    __shared__ float tf[64][65];

    if (blockIdx.x < GATE_BLKS) {
        // ===== gate part: each warp handles 4 tokens; gw loads amortized 4x =====
        int warp = (blockIdx.x * blockDim.x + threadIdx.x) >> 5;  // 0..4095
        int lane = threadIdx.x & 31;
        int tok0 = warp * 4;

        const float4* xr[4];
        __half* xh[4];
#pragma unroll
        for (int j = 0; j < 4; j++) {
            xr[j] = (const float4*)(x + ((size_t)(tok0 + j) << 11));
            xh[j] = g_xh + ((size_t)(tok0 + j) << 11);
        }

        float acc[4][N_EXP];
#pragma unroll
        for (int j = 0; j < 4; j++)
#pragma unroll
            for (int e = 0; e < N_EXP; e++) acc[j][e] = 0.f;

#pragma unroll 4
        for (int i = 0; i < 16; i++) {
            int k4 = lane + 32 * i;
            const float4* g4 = (const float4*)(gw + ((size_t)(4 * k4)) * N_EXP);
            float4 gA[4], gB[4];
#pragma unroll
            for (int r = 0; r < 4; r++) { gA[r] = g4[2 * r]; gB[r] = g4[2 * r + 1]; }
#pragma unroll
            for (int j = 0; j < 4; j++) {
                float4 v = xr[j][k4];
                union { __half2 h[2]; uint2 u; } o;
                o.h[0] = __floats2half2_rn(v.x, v.y);
                o.h[1] = __floats2half2_rn(v.z, v.w);
                *(uint2*)(xh[j] + 4 * k4) = o.u;
                const float* vv = &v.x;
#pragma unroll
                for (int r = 0; r < 4; r++) {
                    float xv = vv[r];
                    acc[j][0] += xv * gA[r].x; acc[j][1] += xv * gA[r].y;
                    acc[j][2] += xv * gA[r].z; acc[j][3] += xv * gA[r].w;
                    acc[j][4] += xv * gB[r].x; acc[j][5] += xv * gB[r].y;
                    acc[j][6] += xv * gB[r].z; acc[j][7] += xv * gB[r].w;
                }
            }
        }
#pragma unroll
        for (int j = 0; j < 4; j++)
#pragma unroll
            for (int e = 0; e < N_EXP; e++)
#pragma unroll
                for (int off = 16; off; off >>= 1)
                    acc[j][e] += __shfl_xor_sync(0xffffffffu, acc[j][e], off);

        if ((lane & 7) == 0) {      // lanes 0,8,16,24 handle tokens 0..3
            int j = lane >> 3;
            float v1 = -1e30f, v2 = -1e30f; int i1 = 0, i2 = 0;
#pragma unroll
            for (int e = 0; e < N_EXP; e++) {
                float v = acc[j][e] + gb[e];
                if (v > v1)      { v2 = v1; i2 = i1; v1 = v; i1 = e; }
                else if (v > v2) { v2 = v;  i2 = e; }
            }
            int t = tok0 + j;
            g_top[t * 2 + 0] = i1;
            g_top[t * 2 + 1] = i2;
            atomicAdd(&g_counts[i1], 1);
            atomicAdd(&g_counts[i2], 1);
        }
    } else {
        // ===== W transpose+convert part: Wt[e][o][d] = fp16(W[e][d][o]) =====
        int b = blockIdx.x - GATE_BLKS;
        int e = b >> 10;               // 1024 tiles per expert
        int rem = b & 1023;
        int d0 = (rem & 31) * 64, o0 = (rem >> 5) * 64;
        const float* we = ew + ((size_t)e * DIM_D + d0) * DIM_O + o0;
        int dd = threadIdx.x >> 2, oq = (threadIdx.x & 3) * 16;
#pragma unroll
        for (int c = 0; c < 4; c++) {
            float4 v = *(const float4*)(we + (size_t)dd * DIM_O + oq + 4 * c);
            tf[dd][oq + 4 * c + 0] = v.x; tf[dd][oq + 4 * c + 1] = v.y;
            tf[dd][oq + 4 * c + 2] = v.z; tf[dd][oq + 4 * c + 3] = v.w;
        }
        __syncthreads();
        int oo = threadIdx.x >> 2, dq = (threadIdx.x & 3) * 16;
        union { __half2 h[8]; uint4 u[2]; } ou;
#pragma unroll
        for (int j = 0; j < 8; j++)
            ou.h[j] = __floats2half2_rn(tf[dq + 2 * j][oo], tf[dq + 2 * j + 1][oo]);
        size_t off = ((size_t)e * DIM_O + o0 + oo) * DIM_D + d0 + dq;
        *(uint4*)(g_wt + off) = ou.u[0];
        *(uint4*)(g_wt + off + 8) = ou.u[1];
    }
}

// ---------------- scan: padded offsets + tile table ----------------
__global__ void scan_k() {
    if (threadIdx.x != 0) return;
    int o = 0, t = 0;
    for (int e = 0; e < N_EXP; e++) {
        g_offsets[e] = o;
        int nt = (g_counts[e] + 127) / 128;
        for (int i = 0; i < nt; i++) { g_tile_e[t] = e; g_tile_r0[t] = o + i * 128; t++; }
        o += nt * 128;
    }
    g_num_tiles = t;
}

// ---------------- scatter ----------------
__global__ void scatter_k() {
    int i = blockIdx.x * blockDim.x + threadIdx.x;
    if (i >= T_TOKENS * 2) return;
    int e = g_top[i];
    int pos = atomicAdd(&g_cursor[e], 1);
    int row = g_offsets[e] + pos;
    g_rows[row] = i >> 1;
    g_pos[i] = row;
}

// ---------------- persistent grouped GEMM: fp16 mma.sync, 4-stage cp.async ----------------
__global__ void __launch_bounds__(256, 1)
moe_hmma(const float* __restrict__ eb) {
    extern __shared__ char sm[];
    char* Asm = sm;
    char* Bsm = sm + NSTAGE * A_STAGE;
    int* toks = (int*)(sm + NSTAGE * (A_STAGE + B_STAGE));
    uint32_t sbA = smem_u32(Asm);
    uint32_t sbB = smem_u32(Bsm);

    int tid = threadIdx.x;
    int warp = tid >> 5, lane = tid & 31;

    // constant mappings
    int prow = tid >> 3;          // producer row 0..31 (+32i)
    int pc   = tid & 7;           // 16B chunk within 128B row
    int adst[4], bdst[8];
#pragma unroll
    for (int i = 0; i < 4; i++) adst[i] = swz(prow + 32 * i, pc);
#pragma unroll
    for (int i = 0; i < 8; i++) bdst[i] = swz(prow + 32 * i, pc);

    int wm = (warp & 3) * 32;
    int wn = (warp >> 2) * 128;
    int arow  = wm + ((lane >> 3) & 1) * 8 + (lane & 7);
    int achi  = lane >> 4;
    int brow_ = ((lane >> 4) << 3) + (lane & 7);
    int bchi  = (lane >> 3) & 1;
    int g = lane >> 2, q = lane & 3;

    int ntN   = g_num_tiles;
    int total = (DIM_O / BN) * ntN;
    int w = blockIdx.x;
    if (w >= total) return;

    // ---- decode + load first tile ----
    int nt = w / ntN, mt = w - nt * ntN;
    int e    = g_tile_e[mt];
    int row0 = g_tile_r0[mt];
    int n0   = nt * BN;
    int lim  = g_offsets[e] + g_counts[e];
    if (tid < BM) toks[tid] = (row0 + tid < lim) ? g_rows[row0 + tid] : -1;
    __syncthreads();

    int atok[4];
    const __half* asrc[4];
    const __half* bsrc[8];
#pragma unroll
    for (int i = 0; i < 4; i++) {
        atok[i] = toks[prow + 32 * i];
        int t = atok[i] < 0 ? 0 : atok[i];
        asrc[i] = g_xh + ((size_t)t << 11) + 8 * pc;
    }
#pragma unroll
    for (int i = 0; i < 8; i++)
        bsrc[i] = g_wt + ((size_t)e * DIM_O + n0 + prow + 32 * i) * DIM_D + 8 * pc;

    // first prologue: stages 0,1,2 <- k-steps 0,1,2
#pragma unroll
    for (int s = 0; s < 3; s++) {
        int k0 = s * BK;
#pragma unroll
        for (int i = 0; i < 4; i++)
            cpa(sbA + s * A_STAGE + adst[i], asrc[i] + k0, atok[i] >= 0 ? 16 : 0);
#pragma unroll
        for (int i = 0; i < 8; i++)
            cpa(sbB + s * B_STAGE + bdst[i], bsrc[i] + k0, 16);
        CP_COMMIT();
    }

    const int NKI = DIM_D / BK;  // 32 (== 0 mod NSTAGE: stage index = ks & 3)

    while (true) {
        // capture current-tile epilogue state (toks will be overwritten by prefetch)
        int ce = e, cn0 = n0, crow0 = row0;

        float acc[2][16][4];
#pragma unroll
        for (int t = 0; t < 2; t++)
#pragma unroll
            for (int n = 0; n < 16; n++)
#pragma unroll
                for (int j = 0; j < 4; j++) acc[t][n][j] = 0.f;

        // ---- mainloop over K ----
        for (int ks = 0; ks < NKI; ks++) {
            int s = ks & 3;
            CP_WAIT2();
            __syncthreads();

            int kn = ks + 3;
            if (kn < NKI) {
                int sn = kn & 3;
                int k0 = kn * BK;
#pragma unroll
                for (int i = 0; i < 4; i++)
                    cpa(sbA + sn * A_STAGE + adst[i], asrc[i] + k0, atok[i] >= 0 ? 16 : 0);
#pragma unroll
                for (int i = 0; i < 8; i++)
                    cpa(sbB + sn * B_STAGE + bdst[i], bsrc[i] + k0, 16);
            }
            CP_COMMIT();

            uint32_t ab = sbA + s * A_STAGE;
            uint32_t bb = sbB + s * B_STAGE;
#pragma unroll
            for (int kb = 0; kb < 4; kb++) {
                uint32_t a[2][4];
#pragma unroll
                for (int tt = 0; tt < 2; tt++)
                    ldsm4(a[tt], ab + swz(arow + 16 * tt, 2 * kb + achi));
#pragma unroll
                for (int ntp = 0; ntp < 8; ntp++) {
                    uint32_t b[4];
                    ldsm4(b, bb + swz(wn + 16 * ntp + brow_, 2 * kb + bchi));
                    mma_f16(acc[0][2 * ntp],     a[0], b[0], b[1]);
                    mma_f16(acc[0][2 * ntp + 1], a[0], b[2], b[3]);
                    mma_f16(acc[1][2 * ntp],     a[1], b[0], b[1]);
                    mma_f16(acc[1][2 * ntp + 1], a[1], b[2], b[3]);
                }
            }
        }

        // ---- prefetch next tile (toks + 3-stage prologue) before epilogue ----
        int wnext = w + gridDim.x;
        bool more = (wnext < total);
        if (more) {
            nt = wnext / ntN; mt = wnext - nt * ntN;
            e    = g_tile_e[mt];
            row0 = g_tile_r0[mt];
            n0   = nt * BN;
            lim  = g_offsets[e] + g_counts[e];
            if (tid < BM) toks[tid] = (row0 + tid < lim) ? g_rows[row0 + tid] : -1;
            __syncthreads();
#pragma unroll
            for (int i = 0; i < 4; i++) {
                atok[i] = toks[prow + 32 * i];
                int t = atok[i] < 0 ? 0 : atok[i];
                asrc[i] = g_xh + ((size_t)t << 11) + 8 * pc;
            }
#pragma unroll
            for (int i = 0; i < 8; i++)
                bsrc[i] = g_wt + ((size_t)e * DIM_O + n0 + prow + 32 * i) * DIM_D + 8 * pc;
#pragma unroll
            for (int s = 0; s < 3; s++) {
                int k0 = s * BK;
#pragma unroll
                for (int i = 0; i < 4; i++)
                    cpa(sbA + s * A_STAGE + adst[i], asrc[i] + k0, atok[i] >= 0 ? 16 : 0);
#pragma unroll
                for (int i = 0; i < 8; i++)
                    cpa(sbB + s * B_STAGE + bdst[i], bsrc[i] + k0, 16);
                CP_COMMIT();
            }
        }

        // ---- epilogue: relu(acc + bias) -> g_operm (fp16) ----
        const float* ebrow = eb + (size_t)ce * DIM_O;
#pragma unroll
        for (int t = 0; t < 2; t++) {
            int ra = crow0 + wm + 16 * t + g;
#pragma unroll
            for (int ntp = 0; ntp < 16; ntp++) {
                int col = cn0 + wn + 8 * ntp + 2 * q;
                float b0v = ebrow[col], b1v = ebrow[col + 1];
                __half2 h0 = __floats2half2_rn(fmaxf(acc[t][ntp][0] + b0v, 0.f),
                                               fmaxf(acc[t][ntp][1] + b1v, 0.f));
                __half2 h1 = __floats2half2_rn(fmaxf(acc[t][ntp][2] + b0v, 0.f),
                                               fmaxf(acc[t][ntp][3] + b1v, 0.f));
                *(__half2*)(g_operm + (size_t)ra * DIM_O + col) = h0;
                *(__half2*)(g_operm + (size_t)(ra + 8) * DIM_O + col) = h1;
            }
        }

        if (!more) break;
        w = wnext;
    }
}

// ---------------- combine: out[t] = 0.5*(row_e1 + row_e2) ----------------
__global__ void combine_k(float* __restrict__ out) {
    int t = blockIdx.x;
    const uint4* a = (const uint4*)(g_operm + (size_t)g_pos[2 * t] * DIM_O);
    const uint4* b = (const uint4*)(g_operm + (size_t)g_pos[2 * t + 1] * DIM_O);
    float4* o = (float4*)(out + (size_t)t * DIM_O);
    int i = threadIdx.x;   // 256 threads x 8 halves = 2048
    union { uint4 u; __half2 h[4]; } va, vb;
    va.u = a[i]; vb.u = b[i];
#pragma unroll
    for (int j = 0; j < 4; j += 2) {
        float2 a0 = __half22float2(va.h[j]),     b0 = __half22float2(vb.h[j]);
        float2 a1 = __half22float2(va.h[j + 1]), b1 = __half22float2(vb.h[j + 1]);
        float4 v;
        v.x = 0.5f * (a0.x + b0.x); v.y = 0.5f * (a0.y + b0.y);
        v.z = 0.5f * (a1.x + b1.x); v.w = 0.5f * (a1.y + b1.y);
        o[2 * i + j / 2] = v;
    }
}

// ---------------- host ----------------
extern "C" void kernel_launch(void* const* d_in, const int* in_sizes, int n_in,
                              void* d_out, int out_size) {
    const float* x  = (const float*)d_in[0];
    const float* gw = (const float*)d_in[1];
    const float* gb = (const float*)d_in[2];
    const float* ew = (const float*)d_in[3];
    const float* eb = (const float*)d_in[4];
    float* out = (float*)d_out;

    static int sms = 0;
    if (sms == 0) {
        cudaDeviceGetAttribute(&sms, cudaDevAttrMultiProcessorCount, 0);
        if (sms <= 0) sms = 148;
        cudaFuncSetAttribute(moe_hmma, cudaFuncAttributeMaxDynamicSharedMemorySize, SMEM_TOTAL);
    }

    init_k<<<1, 32>>>();
    prep_k<<<GATE_BLKS + WT_BLKS, 256>>>(x, gw, gb, ew);
    scan_k<<<1, 1>>>();
    scatter_k<<<(T_TOKENS * 2) / 256, 256>>>();
    moe_hmma<<<sms, 256, SMEM_TOTAL>>>(eb);
    combine_k<<<T_TOKENS, 256>>>(out);
}

// round 13
// speedup vs baseline: 1.0391x; 1.0391x over previous
#include <cuda_runtime.h>
#include <cuda_fp16.h>
#include <cstdint>

// Problem: N=8,S=2048 -> T=16384 tokens, D=O=2048, E=8, top-2
#define T_TOKENS 16384
#define DIM_D    2048
#define DIM_O    2048
#define N_EXP    8
#define MAX_TILES 264               // ceil-per-expert padding worst case
#define R_MAX    (MAX_TILES * 128)  // padded rows

#define BM 128
#define BN 256
#define BK 64
#define NSTAGE 3
#define A_STAGE (BM * BK * 2)       // 16384 B
#define B_STAGE (BN * BK * 2)       // 32768 B
#define SMEM_TOTAL (NSTAGE * (A_STAGE + B_STAGE) + 512)

#define GATE_BLKS (T_TOKENS / 32)   // 512: 8 warps/block x 4 tokens/warp
#define WT_BLKS   (32 * 32 * N_EXP) // 8192

// ---------------- device scratch (static; no allocation) ----------------
__device__ __half g_operm[(size_t)R_MAX * DIM_O];           // relu(XW+b) rows (fp16)
__device__ __half g_xh[(size_t)T_TOKENS * DIM_D];           // x fp16 (token order)
__device__ __half g_wt[(size_t)N_EXP * DIM_O * DIM_D];      // W^T fp16 [e][o][d]
__device__ int g_top[T_TOKENS * 2];
__device__ int g_counts[N_EXP];
__device__ int g_offsets[N_EXP];
__device__ int g_cursor[N_EXP];
__device__ int g_rows[R_MAX];        // padded row -> token (valid only < offset+count)
__device__ int g_pos[T_TOKENS * 2];  // (token,k) -> padded row
__device__ int g_tile_e[MAX_TILES];
__device__ int g_tile_r0[MAX_TILES];
__device__ int g_num_tiles;

// ---------------- helpers ----------------
__device__ __forceinline__ uint32_t smem_u32(const void* p) {
    uint32_t a;
    asm("{ .reg .u64 t; cvta.to.shared.u64 t, %1; cvt.u32.u64 %0, t; }" : "=r"(a) : "l"(p));
    return a;
}
__device__ __forceinline__ void cpa(uint32_t dst, const void* src, int n) {
    asm volatile("cp.async.ca.shared.global [%0], [%1], 16, %2;"
                 :: "r"(dst), "l"(src), "r"(n) : "memory");
}
#define CP_COMMIT() asm volatile("cp.async.commit_group;" ::: "memory")
#define CP_WAIT1()  asm volatile("cp.async.wait_group 1;" ::: "memory")
__device__ __forceinline__ void ldsm4(uint32_t* r, uint32_t addr) {
    asm volatile("ldmatrix.sync.aligned.m8n8.x4.shared.b16 {%0,%1,%2,%3}, [%4];"
                 : "=r"(r[0]), "=r"(r[1]), "=r"(r[2]), "=r"(r[3]) : "r"(addr));
}
__device__ __forceinline__ void mma_f16(float* d, const uint32_t* a, uint32_t b0, uint32_t b1) {
    asm volatile(
        "mma.sync.aligned.m16n8k16.row.col.f32.f16.f16.f32 "
        "{%0,%1,%2,%3}, {%4,%5,%6,%7}, {%8,%9}, {%0,%1,%2,%3};"
        : "+f"(d[0]), "+f"(d[1]), "+f"(d[2]), "+f"(d[3])
        : "r"(a[0]), "r"(a[1]), "r"(a[2]), "r"(a[3]), "r"(b0), "r"(b1));
}
// swizzled byte offset within a stage: row*128 + 16*(chunk ^ (row&7))
__device__ __forceinline__ int swz(int row, int chunk) {
    return row * 128 + ((chunk ^ (row & 7)) << 4);
}

// ---------------- init ----------------
__global__ void init_k() {
    int i = threadIdx.x;
    if (i < N_EXP) { g_counts[i] = 0; g_cursor[i] = 0; }
}

// ---------------- fused prep: gate(+x->fp16, 4 tok/warp)  ||  W transpose+convert ----------------
__global__ void prep_k(const float* __restrict__ x,
                       const float* __restrict__ gw,
                       const float* __restrict__ gb,
                       const float* __restrict__ ew) {
    __shared__ float tf[64][65];

    if (blockIdx.x < GATE_BLKS) {
        // ===== gate part: each warp handles 4 tokens; gw loads amortized 4x =====
        int warp = (blockIdx.x * blockDim.x + threadIdx.x) >> 5;  // 0..4095
        int lane = threadIdx.x & 31;
        int tok0 = warp * 4;

        const float4* xr[4];
        __half* xh[4];
#pragma unroll
        for (int j = 0; j < 4; j++) {
            xr[j] = (const float4*)(x + ((size_t)(tok0 + j) << 11));
            xh[j] = g_xh + ((size_t)(tok0 + j) << 11);
        }

        float acc[4][N_EXP];
#pragma unroll
        for (int j = 0; j < 4; j++)
#pragma unroll
            for (int e = 0; e < N_EXP; e++) acc[j][e] = 0.f;

#pragma unroll 4
        for (int i = 0; i < 16; i++) {
            int k4 = lane + 32 * i;
            const float4* g4 = (const float4*)(gw + ((size_t)(4 * k4)) * N_EXP);
            float4 gA[4], gB[4];
#pragma unroll
            for (int r = 0; r < 4; r++) { gA[r] = g4[2 * r]; gB[r] = g4[2 * r + 1]; }
#pragma unroll
            for (int j = 0; j < 4; j++) {
                float4 v = xr[j][k4];
                union { __half2 h[2]; uint2 u; } o;
                o.h[0] = __floats2half2_rn(v.x, v.y);
                o.h[1] = __floats2half2_rn(v.z, v.w);
                *(uint2*)(xh[j] + 4 * k4) = o.u;
                const float* vv = &v.x;
#pragma unroll
                for (int r = 0; r < 4; r++) {
                    float xv = vv[r];
                    acc[j][0] += xv * gA[r].x; acc[j][1] += xv * gA[r].y;
                    acc[j][2] += xv * gA[r].z; acc[j][3] += xv * gA[r].w;
                    acc[j][4] += xv * gB[r].x; acc[j][5] += xv * gB[r].y;
                    acc[j][6] += xv * gB[r].z; acc[j][7] += xv * gB[r].w;
                }
            }
        }
#pragma unroll
        for (int j = 0; j < 4; j++)
#pragma unroll
            for (int e = 0; e < N_EXP; e++)
#pragma unroll
                for (int off = 16; off; off >>= 1)
                    acc[j][e] += __shfl_xor_sync(0xffffffffu, acc[j][e], off);

        if ((lane & 7) == 0) {      // lanes 0,8,16,24 handle tokens 0..3
            int j = lane >> 3;
            float v1 = -1e30f, v2 = -1e30f; int i1 = 0, i2 = 0;
#pragma unroll
            for (int e = 0; e < N_EXP; e++) {
                float v = acc[j][e] + gb[e];
                if (v > v1)      { v2 = v1; i2 = i1; v1 = v; i1 = e; }
                else if (v > v2) { v2 = v;  i2 = e; }
            }
            int t = tok0 + j;
            g_top[t * 2 + 0] = i1;
            g_top[t * 2 + 1] = i2;
            atomicAdd(&g_counts[i1], 1);
            atomicAdd(&g_counts[i2], 1);
        }
    } else {
        // ===== W transpose+convert part: Wt[e][o][d] = fp16(W[e][d][o]) =====
        int b = blockIdx.x - GATE_BLKS;
        int e = b >> 10;               // 1024 tiles per expert
        int rem = b & 1023;
        int d0 = (rem & 31) * 64, o0 = (rem >> 5) * 64;
        const float* we = ew + ((size_t)e * DIM_D + d0) * DIM_O + o0;
        int dd = threadIdx.x >> 2, oq = (threadIdx.x & 3) * 16;
#pragma unroll
        for (int c = 0; c < 4; c++) {
            float4 v = *(const float4*)(we + (size_t)dd * DIM_O + oq + 4 * c);
            tf[dd][oq + 4 * c + 0] = v.x; tf[dd][oq + 4 * c + 1] = v.y;
            tf[dd][oq + 4 * c + 2] = v.z; tf[dd][oq + 4 * c + 3] = v.w;
        }
        __syncthreads();
        int oo = threadIdx.x >> 2, dq = (threadIdx.x & 3) * 16;
        union { __half2 h[8]; uint4 u[2]; } ou;
#pragma unroll
        for (int j = 0; j < 8; j++)
            ou.h[j] = __floats2half2_rn(tf[dq + 2 * j][oo], tf[dq + 2 * j + 1][oo]);
        size_t off = ((size_t)e * DIM_O + o0 + oo) * DIM_D + d0 + dq;
        *(uint4*)(g_wt + off) = ou.u[0];
        *(uint4*)(g_wt + off + 8) = ou.u[1];
    }
}

// ---------------- scan: padded offsets + tile table ----------------
__global__ void scan_k() {
    if (threadIdx.x != 0) return;
    int o = 0, t = 0;
    for (int e = 0; e < N_EXP; e++) {
        g_offsets[e] = o;
        int nt = (g_counts[e] + 127) / 128;
        for (int i = 0; i < nt; i++) { g_tile_e[t] = e; g_tile_r0[t] = o + i * 128; t++; }
        o += nt * 128;
    }
    g_num_tiles = t;
}

// ---------------- scatter ----------------
__global__ void scatter_k() {
    int i = blockIdx.x * blockDim.x + threadIdx.x;
    if (i >= T_TOKENS * 2) return;
    int e = g_top[i];
    int pos = atomicAdd(&g_cursor[e], 1);
    int row = g_offsets[e] + pos;
    g_rows[row] = i >> 1;
    g_pos[i] = row;
}

// ---------------- persistent grouped GEMM: fp16 mma.sync, 64x64 warp tiles ----------------
__global__ void __launch_bounds__(256, 1)
moe_hmma(const float* __restrict__ eb) {
    extern __shared__ char sm[];
    char* Asm = sm;
    char* Bsm = sm + NSTAGE * A_STAGE;
    int* toks = (int*)(sm + NSTAGE * (A_STAGE + B_STAGE));
    uint32_t sbA = smem_u32(Asm);
    uint32_t sbB = smem_u32(Bsm);

    int tid = threadIdx.x;
    int warp = tid >> 5, lane = tid & 31;

    // constant mappings
    int prow = tid >> 3;          // producer row 0..31 (+32i)
    int pc   = tid & 7;           // 16B chunk within 128B row
    int adst[4], bdst[8];
#pragma unroll
    for (int i = 0; i < 4; i++) adst[i] = swz(prow + 32 * i, pc);
#pragma unroll
    for (int i = 0; i < 8; i++) bdst[i] = swz(prow + 32 * i, pc);

    // 2 M-warps x 4 N-warps, warp tile 64x64
    int wm = (warp & 1) * 64;
    int wn = (warp >> 1) * 64;
    int arow  = wm + (lane & 15);
    int achi  = lane >> 4;
    int brow_ = ((lane >> 4) << 3) + (lane & 7);
    int bchi  = (lane >> 3) & 1;
    int g = lane >> 2, q = lane & 3;

    int ntN   = g_num_tiles;
    int total = (DIM_O / BN) * ntN;
    int w = blockIdx.x;
    if (w >= total) return;

    // ---- decode + load first tile ----
    int nt = w / ntN, mt = w - nt * ntN;
    int e    = g_tile_e[mt];
    int row0 = g_tile_r0[mt];
    int n0   = nt * BN;
    int lim  = g_offsets[e] + g_counts[e];
    if (tid < BM) toks[tid] = (row0 + tid < lim) ? g_rows[row0 + tid] : -1;
    __syncthreads();

    int atok[4];
    const __half* asrc[4];
    const __half* bsrc[8];
#pragma unroll
    for (int i = 0; i < 4; i++) {
        atok[i] = toks[prow + 32 * i];
        int t = atok[i] < 0 ? 0 : atok[i];
        asrc[i] = g_xh + ((size_t)t << 11) + 8 * pc;
    }
#pragma unroll
    for (int i = 0; i < 8; i++)
        bsrc[i] = g_wt + ((size_t)e * DIM_O + n0 + prow + 32 * i) * DIM_D + 8 * pc;

    int st = 0;
    // first prologue: stages st, st+1 <- k-steps 0,1
    {
        int s2 = st + 1; if (s2 >= NSTAGE) s2 -= NSTAGE;
#pragma unroll
        for (int i = 0; i < 4; i++)
            cpa(sbA + st * A_STAGE + adst[i], asrc[i], atok[i] >= 0 ? 16 : 0);
#pragma unroll
        for (int i = 0; i < 8; i++)
            cpa(sbB + st * B_STAGE + bdst[i], bsrc[i], 16);
        CP_COMMIT();
#pragma unroll
        for (int i = 0; i < 4; i++)
            cpa(sbA + s2 * A_STAGE + adst[i], asrc[i] + BK, atok[i] >= 0 ? 16 : 0);
#pragma unroll
        for (int i = 0; i < 8; i++)
            cpa(sbB + s2 * B_STAGE + bdst[i], bsrc[i] + BK, 16);
        CP_COMMIT();
    }

    const int NKI = DIM_D / BK;  // 32

    while (true) {
        // capture current-tile epilogue state (toks will be overwritten by prefetch)
        int ce = e, cn0 = n0, crow0 = row0;

        float acc[4][8][4];
#pragma unroll
        for (int t = 0; t < 4; t++)
#pragma unroll
            for (int n = 0; n < 8; n++)
#pragma unroll
                for (int j = 0; j < 4; j++) acc[t][n][j] = 0.f;

        // ---- mainloop over K ----
        int s = st;
        for (int ks = 0; ks < NKI; ks++) {
            CP_WAIT1();
            __syncthreads();

            int kn = ks + 2;
            if (kn < NKI) {
                int sn = s + 2; if (sn >= NSTAGE) sn -= NSTAGE;
                int k0 = kn * BK;
#pragma unroll
                for (int i = 0; i < 4; i++)
                    cpa(sbA + sn * A_STAGE + adst[i], asrc[i] + k0, atok[i] >= 0 ? 16 : 0);
#pragma unroll
                for (int i = 0; i < 8; i++)
                    cpa(sbB + sn * B_STAGE + bdst[i], bsrc[i] + k0, 16);
            }
            CP_COMMIT();

            uint32_t ab = sbA + s * A_STAGE;
            uint32_t bb = sbB + s * B_STAGE;
#pragma unroll
            for (int kb = 0; kb < 4; kb++) {
                uint32_t a[4][4];
#pragma unroll
                for (int tt = 0; tt < 4; tt++)
                    ldsm4(a[tt], ab + swz(arow + 16 * tt, 2 * kb + achi));
#pragma unroll
                for (int ntp = 0; ntp < 4; ntp++) {
                    uint32_t b[4];
                    ldsm4(b, bb + swz(wn + 16 * ntp + brow_, 2 * kb + bchi));
#pragma unroll
                    for (int tt = 0; tt < 4; tt++) {
                        mma_f16(acc[tt][2 * ntp],     a[tt], b[0], b[1]);
                        mma_f16(acc[tt][2 * ntp + 1], a[tt], b[2], b[3]);
                    }
                }
            }
            if (++s == NSTAGE) s = 0;
        }
        st = s;  // advanced by 32 mod 3

        // ---- prefetch next tile (toks + prologue) before epilogue ----
        int wnext = w + gridDim.x;
        bool more = (wnext < total);
        if (more) {
            nt = wnext / ntN; mt = wnext - nt * ntN;
            e    = g_tile_e[mt];
            row0 = g_tile_r0[mt];
            n0   = nt * BN;
            lim  = g_offsets[e] + g_counts[e];
            if (tid < BM) toks[tid] = (row0 + tid < lim) ? g_rows[row0 + tid] : -1;
            __syncthreads();
#pragma unroll
            for (int i = 0; i < 4; i++) {
                atok[i] = toks[prow + 32 * i];
                int t = atok[i] < 0 ? 0 : atok[i];
                asrc[i] = g_xh + ((size_t)t << 11) + 8 * pc;
            }
#pragma unroll
            for (int i = 0; i < 8; i++)
                bsrc[i] = g_wt + ((size_t)e * DIM_O + n0 + prow + 32 * i) * DIM_D + 8 * pc;
            int s2 = st + 1; if (s2 >= NSTAGE) s2 -= NSTAGE;
#pragma unroll
            for (int i = 0; i < 4; i++)
                cpa(sbA + st * A_STAGE + adst[i], asrc[i], atok[i] >= 0 ? 16 : 0);
#pragma unroll
            for (int i = 0; i < 8; i++)
                cpa(sbB + st * B_STAGE + bdst[i], bsrc[i], 16);
            CP_COMMIT();
#pragma unroll
            for (int i = 0; i < 4; i++)
                cpa(sbA + s2 * A_STAGE + adst[i], asrc[i] + BK, atok[i] >= 0 ? 16 : 0);
#pragma unroll
            for (int i = 0; i < 8; i++)
                cpa(sbB + s2 * B_STAGE + bdst[i], bsrc[i] + BK, 16);
            CP_COMMIT();
        }

        // ---- epilogue: relu(acc + bias) -> g_operm (fp16) ----
        const float* ebrow = eb + (size_t)ce * DIM_O;
#pragma unroll
        for (int t = 0; t < 4; t++) {
            int ra = crow0 + wm + 16 * t + g;
#pragma unroll
            for (int ntp = 0; ntp < 8; ntp++) {
                int col = cn0 + wn + 8 * ntp + 2 * q;
                float b0v = ebrow[col], b1v = ebrow[col + 1];
                __half2 h0 = __floats2half2_rn(fmaxf(acc[t][ntp][0] + b0v, 0.f),
                                               fmaxf(acc[t][ntp][1] + b1v, 0.f));
                __half2 h1 = __floats2half2_rn(fmaxf(acc[t][ntp][2] + b0v, 0.f),
                                               fmaxf(acc[t][ntp][3] + b1v, 0.f));
                *(__half2*)(g_operm + (size_t)ra * DIM_O + col) = h0;
                *(__half2*)(g_operm + (size_t)(ra + 8) * DIM_O + col) = h1;
            }
        }

        if (!more) break;
        w = wnext;
    }
}

// ---------------- combine: out[t] = 0.5*(row_e1 + row_e2) ----------------
__global__ void combine_k(float* __restrict__ out) {
    int t = blockIdx.x;
    const uint4* a = (const uint4*)(g_operm + (size_t)g_pos[2 * t] * DIM_O);
    const uint4* b = (const uint4*)(g_operm + (size_t)g_pos[2 * t + 1] * DIM_O);
    float4* o = (float4*)(out + (size_t)t * DIM_O);
    int i = threadIdx.x;   // 256 threads x 8 halves = 2048
    union { uint4 u; __half2 h[4]; } va, vb;
    va.u = a[i]; vb.u = b[i];
#pragma unroll
    for (int j = 0; j < 4; j += 2) {
        float2 a0 = __half22float2(va.h[j]),     b0 = __half22float2(vb.h[j]);
        float2 a1 = __half22float2(va.h[j + 1]), b1 = __half22float2(vb.h[j + 1]);
        float4 v;
        v.x = 0.5f * (a0.x + b0.x); v.y = 0.5f * (a0.y + b0.y);
        v.z = 0.5f * (a1.x + b1.x); v.w = 0.5f * (a1.y + b1.y);
        o[2 * i + j / 2] = v;
    }
}

// ---------------- host ----------------
extern "C" void kernel_launch(void* const* d_in, const int* in_sizes, int n_in,
                              void* d_out, int out_size) {
    const float* x  = (const float*)d_in[0];
    const float* gw = (const float*)d_in[1];
    const float* gb = (const float*)d_in[2];
    const float* ew = (const float*)d_in[3];
    const float* eb = (const float*)d_in[4];
    float* out = (float*)d_out;

    static int sms = 0;
    if (sms == 0) {
        cudaDeviceGetAttribute(&sms, cudaDevAttrMultiProcessorCount, 0);
        if (sms <= 0) sms = 148;
        cudaFuncSetAttribute(moe_hmma, cudaFuncAttributeMaxDynamicSharedMemorySize, SMEM_TOTAL);
    }

    init_k<<<1, 32>>>();
    prep_k<<<GATE_BLKS + WT_BLKS, 256>>>(x, gw, gb, ew);
    scan_k<<<1, 1>>>();
    scatter_k<<<(T_TOKENS * 2) / 256, 256>>>();
    moe_hmma<<<sms, 256, SMEM_TOTAL>>>(eb);
    combine_k<<<T_TOKENS, 256>>>(out);
}